// round 7
// baseline (speedup 1.0000x reference)
#include <cuda_runtime.h>
#include <cuda_bf16.h>

#define N_NODES 100000
#define N_EDGES 1600000
#define IN_FT   128
#define OUT_FT  32

#define TILE_NODES 256
#define KTILE      32          // k per phase (8 float4)
#define ROW_F4     9           // 8 float4 + 1 pad -> conflict-free LDS.128

#define CAP        64          // slots per row; Poisson(16) => P(overflow) ~ 1e-18

// Device-global scratch (no allocs allowed).
__device__ float  g_support[(size_t)N_NODES * OUT_FT];        // 12.8 MB
__device__ float2 g_binned[(size_t)N_NODES * CAP];            // 51.2 MB
__device__ int    g_cnt[N_NODES];
__device__ int    g_ovf_cnt;
__device__ int    g_ovf_row[N_EDGES];                         // correctness fallback
__device__ int    g_ovf_col[N_EDGES];
__device__ float  g_ovf_val[N_EDGES];

// ---------------------------------------------------------------------------
// Kernel 0: zero per-row counters + overflow counter.
// ---------------------------------------------------------------------------
__global__ void gcn_zero_kernel() {
    int i = blockIdx.x * blockDim.x + threadIdx.x;
    if (i < N_NODES) g_cnt[i] = 0;
    if (i == 0) g_ovf_cnt = 0;
}

// ---------------------------------------------------------------------------
// Kernel 1: support = seq @ W. Register-tiled: 256 threads, 256 nodes/block.
// Thread (n_slot = tid>>2, colgrp = tid&3) computes 4 nodes x 8 cols.
// ---------------------------------------------------------------------------
__global__ __launch_bounds__(256, 3) void gcn_gemm_kernel(
        const float* __restrict__ seq,
        const float* __restrict__ W) {
    __shared__ float4 ssm[TILE_NODES * ROW_F4];   // 36 KB
    __shared__ float  Wsm[KTILE * OUT_FT];        // 4 KB

    const int tid = threadIdx.x;
    const int node_base = blockIdx.x * TILE_NODES;
    const int n_slot = tid >> 2;          // 0..63
    const int j0     = (tid & 3) * 8;     // 0,8,16,24

    float acc[4][8];
    #pragma unroll
    for (int i = 0; i < 4; i++)
        #pragma unroll
        for (int j = 0; j < 8; j++) acc[i][j] = 0.f;

    const float4* seq4 = reinterpret_cast<const float4*>(seq);

    for (int kp = 0; kp < IN_FT / KTILE; kp++) {
        __syncthreads();

        reinterpret_cast<float4*>(Wsm)[tid] =
            reinterpret_cast<const float4*>(W)[kp * (KTILE * OUT_FT / 4) + tid];

        #pragma unroll
        for (int t = 0; t < 8; t++) {
            int idx = tid + t * 256;
            int row = idx >> 3;
            int k4  = idx & 7;
            int node = node_base + row;
            float4 v = make_float4(0.f, 0.f, 0.f, 0.f);
            if (node < N_NODES)
                v = seq4[(size_t)node * (IN_FT / 4) + kp * 8 + k4];
            ssm[row * ROW_F4 + k4] = v;
        }
        __syncthreads();

        #pragma unroll 2
        for (int k4 = 0; k4 < KTILE / 4; k4++) {
            float4 a0 = ssm[(n_slot      ) * ROW_F4 + k4];
            float4 a1 = ssm[(n_slot +  64) * ROW_F4 + k4];
            float4 a2 = ssm[(n_slot + 128) * ROW_F4 + k4];
            float4 a3 = ssm[(n_slot + 192) * ROW_F4 + k4];
            float a[4][4] = {{a0.x, a0.y, a0.z, a0.w},
                             {a1.x, a1.y, a1.z, a1.w},
                             {a2.x, a2.y, a2.z, a2.w},
                             {a3.x, a3.y, a3.z, a3.w}};
            #pragma unroll
            for (int kk = 0; kk < 4; kk++) {
                int k = k4 * 4 + kk;
                float4 w0 = *reinterpret_cast<const float4*>(&Wsm[k * OUT_FT + j0]);
                float4 w1 = *reinterpret_cast<const float4*>(&Wsm[k * OUT_FT + j0 + 4]);
                #pragma unroll
                for (int i = 0; i < 4; i++) {
                    acc[i][0] = fmaf(a[i][kk], w0.x, acc[i][0]);
                    acc[i][1] = fmaf(a[i][kk], w0.y, acc[i][1]);
                    acc[i][2] = fmaf(a[i][kk], w0.z, acc[i][2]);
                    acc[i][3] = fmaf(a[i][kk], w0.w, acc[i][3]);
                    acc[i][4] = fmaf(a[i][kk], w1.x, acc[i][4]);
                    acc[i][5] = fmaf(a[i][kk], w1.y, acc[i][5]);
                    acc[i][6] = fmaf(a[i][kk], w1.z, acc[i][6]);
                    acc[i][7] = fmaf(a[i][kk], w1.w, acc[i][7]);
                }
            }
        }
    }

    #pragma unroll
    for (int i = 0; i < 4; i++) {
        int node = node_base + n_slot + 64 * i;
        if (node < N_NODES) {
            float4* dst = reinterpret_cast<float4*>(&g_support[(size_t)node * OUT_FT + j0]);
            dst[0] = make_float4(acc[i][0], acc[i][1], acc[i][2], acc[i][3]);
            dst[1] = make_float4(acc[i][4], acc[i][5], acc[i][6], acc[i][7]);
        }
    }
}

// ---------------------------------------------------------------------------
// Kernel 2: bin edges by destination row. 1 thread/edge.
// Slot = {col bits, val}. Overflow (never in practice) -> global list.
// ---------------------------------------------------------------------------
__global__ __launch_bounds__(256) void gcn_bin_kernel(
        const int*   __restrict__ erow,
        const int*   __restrict__ ecol,
        const float* __restrict__ eval) {
    int e = blockIdx.x * blockDim.x + threadIdx.x;
    if (e >= N_EDGES) return;

    int r = erow[e];
    int c = ecol[e];
    float v = eval[e];

    int pos = atomicAdd(&g_cnt[r], 1);
    if (pos < CAP) {
        g_binned[(size_t)r * CAP + pos] = make_float2(__int_as_float(c), v);
    } else {
        int o = atomicAdd(&g_ovf_cnt, 1);
        g_ovf_row[o] = r;
        g_ovf_col[o] = c;
        g_ovf_val[o] = v;
    }
}

// ---------------------------------------------------------------------------
// Kernel 3: gather + fused ReLU. One warp per row, lane = output feature.
// Slot reads broadcast; support reads 128B coalesced. Unroll x4 for MLP.
// No atomics on out; every row written exactly once.
// ---------------------------------------------------------------------------
__global__ __launch_bounds__(256) void gcn_gather_kernel(float* __restrict__ out) {
    int warp = (blockIdx.x * blockDim.x + threadIdx.x) >> 5;
    int lane = threadIdx.x & 31;
    if (warp >= N_NODES) return;

    int deg = g_cnt[warp];
    int n = deg < CAP ? deg : CAP;

    const float2* slots = &g_binned[(size_t)warp * CAP];
    float acc = 0.f;

    int e = 0;
    for (; e + 4 <= n; e += 4) {
        float2 s0 = slots[e + 0];
        float2 s1 = slots[e + 1];
        float2 s2 = slots[e + 2];
        float2 s3 = slots[e + 3];
        float f0 = g_support[(size_t)__float_as_int(s0.x) * OUT_FT + lane];
        float f1 = g_support[(size_t)__float_as_int(s1.x) * OUT_FT + lane];
        float f2 = g_support[(size_t)__float_as_int(s2.x) * OUT_FT + lane];
        float f3 = g_support[(size_t)__float_as_int(s3.x) * OUT_FT + lane];
        acc = fmaf(s0.y, f0, acc);
        acc = fmaf(s1.y, f1, acc);
        acc = fmaf(s2.y, f2, acc);
        acc = fmaf(s3.y, f3, acc);
    }
    for (; e < n; e++) {
        float2 s = slots[e];
        acc = fmaf(s.y, g_support[(size_t)__float_as_int(s.x) * OUT_FT + lane], acc);
    }

    // Correctness fallback: apply any overflow edges targeting this row.
    int nov = g_ovf_cnt;
    if (nov > 0) {
        for (int i = 0; i < nov; i++) {
            if (g_ovf_row[i] == warp)
                acc = fmaf(g_ovf_val[i],
                           g_support[(size_t)g_ovf_col[i] * OUT_FT + lane], acc);
        }
    }

    out[(size_t)warp * OUT_FT + lane] = fmaxf(acc, 0.f);
}

extern "C" void kernel_launch(void* const* d_in, const int* in_sizes, int n_in,
                              void* d_out, int out_size) {
    const float* seq  = (const float*)d_in[0];
    const float* W    = (const float*)d_in[1];
    const int*   erow = (const int*)d_in[2];
    const int*   ecol = (const int*)d_in[3];
    const float* eval = (const float*)d_in[4];
    float* out = (float*)d_out;

    // Zero counters.
    gcn_zero_kernel<<<(N_NODES + 255) / 256, 256>>>();

    // GEMM: support = seq @ W.
    gcn_gemm_kernel<<<(N_NODES + TILE_NODES - 1) / TILE_NODES, 256>>>(seq, W);

    // Bin edges by row.
    gcn_bin_kernel<<<(N_EDGES + 255) / 256, 256>>>(erow, ecol, eval);

    // Gather + ReLU (writes every output element exactly once).
    {
        int warps_per_block = 256 / 32;
        int blocks = (N_NODES + warps_per_block - 1) / warps_per_block;
        gcn_gather_kernel<<<blocks, 256>>>(out);
    }
}